// round 12
// baseline (speedup 1.0000x reference)
#include <cuda_runtime.h>
#include <cstdint>

#define DF 128
#define MAXN 50000
#define MAXE 800000

// Scratch (allocation-free rule: __device__ globals)
__device__ __align__(16) float g_xw[MAXN * DF];    // x @ Wg (no dinv)
__device__ float g_dinv[MAXN];
__device__ int   g_ecnt[MAXN];
__device__ int   g_off[MAXN + 1];
__device__ int   g_cur[MAXN];
__device__ int   g_esrc[MAXE];
__device__ int   g_bsum[64];
__device__ int   g_total;

// Packed fp32x2 FMA (SASS FFMA2): c += a * b on both lanes, exact fp32.
__device__ __forceinline__ void ffma2(float2& c, const float2 a, const float2 b) {
    asm("fma.rn.f32x2 %0, %1, %2, %0;"
        : "+l"(reinterpret_cast<unsigned long long&>(c))
        : "l"(reinterpret_cast<const unsigned long long&>(a)),
          "l"(reinterpret_cast<const unsigned long long&>(b)));
}

// Stream + events for graph-captured fork/join (created at load time).
static cudaStream_t g_s2;
static cudaEvent_t g_ev_root, g_ev_gemm;
static struct StreamInit {
    StreamInit() {
        cudaStreamCreateWithFlags(&g_s2, cudaStreamNonBlocking);
        cudaEventCreateWithFlags(&g_ev_root, cudaEventDisableTiming);
        cudaEventCreateWithFlags(&g_ev_gemm, cudaEventDisableTiming);
    }
} g_stream_init;

// ---------------------------------------------------------------------------
__global__ void k_count(const int* __restrict__ ei, int e) {
    int i = blockIdx.x * blockDim.x + threadIdx.x;
    if (i < e) atomicAdd(&g_ecnt[ei[e + i]], 1);
}

__global__ void k_dinv(int n) {
    int i = blockIdx.x * blockDim.x + threadIdx.x;
    if (i < n) g_dinv[i] = rsqrtf((float)(g_ecnt[i] + 1));  // +1 self loop
}

__global__ __launch_bounds__(1024) void k_scan1(int n) {
    __shared__ int wsum[32];
    int tid = threadIdx.x, lane = tid & 31, wid = tid >> 5;
    int i = blockIdx.x * 1024 + tid;
    int v = (i < n) ? g_ecnt[i] : 0;
    int s = v;
#pragma unroll
    for (int d = 1; d < 32; d <<= 1) {
        int t = __shfl_up_sync(0xffffffffu, s, d);
        if (lane >= d) s += t;
    }
    if (lane == 31) wsum[wid] = s;
    __syncthreads();
    if (wid == 0) {
        int t = wsum[lane];
#pragma unroll
        for (int d = 1; d < 32; d <<= 1) {
            int u = __shfl_up_sync(0xffffffffu, t, d);
            if (lane >= d) t += u;
        }
        wsum[lane] = t;
    }
    __syncthreads();
    int excl = s - v + (wid ? wsum[wid - 1] : 0);
    if (i < n) g_off[i] = excl;
    if (tid == 1023) g_bsum[blockIdx.x] = excl + v;
}

__global__ void k_scan2(int nb) {
    if (threadIdx.x == 0 && blockIdx.x == 0) {
        int run = 0;
        for (int i = 0; i < nb; i++) { int t = g_bsum[i]; g_bsum[i] = run; run += t; }
        g_total = run;
    }
}

__global__ __launch_bounds__(1024) void k_scan3(int n) {
    int i = blockIdx.x * 1024 + threadIdx.x;
    if (i < n) {
        int off = g_off[i] + g_bsum[blockIdx.x];
        g_off[i] = off;
        g_cur[i] = off;
    }
    if (i == 0) g_off[n] = g_total;
}

__global__ void k_fill(const int* __restrict__ ei, int e) {
    int i = blockIdx.x * blockDim.x + threadIdx.x;
    if (i < e) {
        int s = ei[i];
        int d = ei[e + i];
        int pos = atomicAdd(&g_cur[d], 1);
        g_esrc[pos] = s;
    }
}

// ---------------------------------------------------------------------------
// Compute body shared by all GEMM loops: acc[ri] += x-broadcast * w
__device__ __forceinline__ void gemm_step8(float2 (*acc)[2], const float* hbase,
                                           int koff, const float4* wv) {
#pragma unroll
    for (int ri = 0; ri < 8; ri++) {
        float4 xv = *(const float4*)(hbase + ri * 128 + koff);
        ffma2(acc[ri][0], make_float2(xv.x, xv.x), make_float2(wv[0].x, wv[0].y));
        ffma2(acc[ri][1], make_float2(xv.x, xv.x), make_float2(wv[0].z, wv[0].w));
        ffma2(acc[ri][0], make_float2(xv.y, xv.y), make_float2(wv[1].x, wv[1].y));
        ffma2(acc[ri][1], make_float2(xv.y, xv.y), make_float2(wv[1].z, wv[1].w));
        ffma2(acc[ri][0], make_float2(xv.z, xv.z), make_float2(wv[2].x, wv[2].y));
        ffma2(acc[ri][1], make_float2(xv.z, xv.z), make_float2(wv[2].z, wv[2].w));
        ffma2(acc[ri][0], make_float2(xv.w, xv.w), make_float2(wv[3].x, wv[3].y));
        ffma2(acc[ri][1], make_float2(xv.w, xv.w), make_float2(wv[3].z, wv[3].w));
    }
}

// xw = x @ Wg. 64 rows/block, 256 threads (8 warps), 2 CTA/SM.
// Weight fragments register-double-buffered across k-steps.
__global__ __launch_bounds__(256) void k_gemm_xw(const float* __restrict__ x,
                                                 const float* __restrict__ Wg,
                                                 int n) {
    extern __shared__ float sm[];
    float* ws = sm;              // [128][128] 64KB
    float* xs = sm + 16384;      // [64][128]  32KB
    int tid = threadIdx.x;

    float4* ws4 = (float4*)ws;
    const float4* Wg4 = (const float4*)Wg;
    for (int i = tid; i < 4096; i += 256) ws4[i] = Wg4[i];

    int rbase = blockIdx.x * 64;
    float4* xs4 = (float4*)xs;
    const float4* x4 = (const float4*)x;
    for (int i = tid; i < 2048; i += 256) {
        int r = rbase + (i >> 5);
        xs4[i] = (r < n) ? x4[(size_t)r * 32 + (i & 31)]
                         : make_float4(0.f, 0.f, 0.f, 0.f);
    }
    __syncthreads();

    int w = tid >> 5, lane = tid & 31;
    float2 acc[8][2];
#pragma unroll
    for (int ri = 0; ri < 8; ri++) {
        acc[ri][0] = make_float2(0.f, 0.f);
        acc[ri][1] = make_float2(0.f, 0.f);
    }

    const float* xbase = xs + w * 8 * 128;
    float4 wv[4];
#pragma unroll
    for (int kk = 0; kk < 4; kk++) wv[kk] = ((const float4*)(ws + kk * 128))[lane];
#pragma unroll 2
    for (int k0 = 0; k0 < 124; k0 += 4) {
        float4 wn[4];
#pragma unroll
        for (int kk = 0; kk < 4; kk++)
            wn[kk] = ((const float4*)(ws + (k0 + 4 + kk) * 128))[lane];
        gemm_step8(acc, xbase, k0, wv);
#pragma unroll
        for (int kk = 0; kk < 4; kk++) wv[kk] = wn[kk];
    }
    gemm_step8(acc, xbase, 124, wv);

#pragma unroll
    for (int ri = 0; ri < 8; ri++) {
        int r = rbase + w * 8 + ri;
        if (r < n) {
            float4 o = make_float4(acc[ri][0].x, acc[ri][0].y,
                                   acc[ri][1].x, acc[ri][1].y);
            ((float4*)(g_xw + (size_t)r * 128))[lane] = o;
        }
    }
}

// ---------------------------------------------------------------------------
// Fused CSR-gather + epilogue + 3-layer MLP. 64 nodes/CTA, 256 threads,
// 2 CTAs/SM. Gather double-buffered (next 4 edges prefetched while the
// current 4 accumulate); weight fragments double-buffered in stages B/C.
__global__ __launch_bounds__(256, 2) void k_mlp(const float* __restrict__ x,
                                                const float* __restrict__ bg,
                                                const float* __restrict__ W1,
                                                const float* __restrict__ b1,
                                                const float* __restrict__ W2,
                                                const float* __restrict__ b2,
                                                const float* __restrict__ W3,
                                                const float* __restrict__ b3,
                                                float* __restrict__ out, int n) {
    extern __shared__ float sm[];
    float* wbuf = sm;            // 8192 floats (32KB): W1 half / W2
    float* sh   = wbuf + 8192;   // 8192: h [64][128]; later h2 [64][64]
    float* sh1  = sh + 8192;     // 8192: h1 [64][128]
    float* sW3 = sh1 + 8192;     // 128
    float* sb1 = sW3 + 128;      // 128
    float* sbg = sb1 + 128;      // 128
    float* sb2 = sbg + 128;      // 64
    float* sb3 = sb2 + 64;       // 2
    int tid = threadIdx.x;
    int w = tid >> 5, lane = tid & 31;

    if (tid < 128) { sW3[tid] = W3[tid]; sb1[tid] = b1[tid]; sbg[tid] = bg[tid]; }
    else if (tid < 192) sb2[tid - 128] = b2[tid - 128];
    else if (tid < 194) sb3[tid - 192] = b3[tid - 192];
    int rbase = blockIdx.x * 64;
    __syncthreads();

    // ---- stage A: CSR gather + h = relu(dinv*agg + bg) + x, 8 nodes/warp ----
    {
        const float4* xw4 = (const float4*)g_xw;
        const float4* x4 = (const float4*)x;
        float2 bgv = make_float2(sbg[lane * 4 + 0], sbg[lane * 4 + 1]);
        float2 bgv2 = make_float2(sbg[lane * 4 + 2], sbg[lane * 4 + 3]);
#pragma unroll 1
        for (int ri = 0; ri < 8; ri++) {
            int rr = w * 8 + ri;
            int node = rbase + rr;
            float4 hv = make_float4(0.f, 0.f, 0.f, 0.f);
            if (node < n) {
                float dvd = g_dinv[node];
                float4 acc = xw4[(size_t)node * 32 + lane];  // self loop
                acc.x *= dvd; acc.y *= dvd; acc.z *= dvd; acc.w *= dvd;
                int beg = g_off[node], end = g_off[node + 1];
                int j = beg;
                int jend = beg + ((end - beg) & ~3);
                if (j < jend) {
                    // prime the pipe: block 0
                    int s0 = g_esrc[j], s1 = g_esrc[j + 1];
                    int s2 = g_esrc[j + 2], s3 = g_esrc[j + 3];
                    float d0 = g_dinv[s0], d1 = g_dinv[s1];
                    float d2 = g_dinv[s2], d3 = g_dinv[s3];
                    float4 v0 = xw4[(size_t)s0 * 32 + lane];
                    float4 v1 = xw4[(size_t)s1 * 32 + lane];
                    float4 v2 = xw4[(size_t)s2 * 32 + lane];
                    float4 v3 = xw4[(size_t)s3 * 32 + lane];
                    for (j += 4; j < jend; j += 4) {
                        // prefetch block k+1 while accumulating block k
                        int t0 = g_esrc[j], t1 = g_esrc[j + 1];
                        int t2 = g_esrc[j + 2], t3 = g_esrc[j + 3];
                        float e0 = g_dinv[t0], e1 = g_dinv[t1];
                        float e2 = g_dinv[t2], e3 = g_dinv[t3];
                        float4 u0 = xw4[(size_t)t0 * 32 + lane];
                        float4 u1 = xw4[(size_t)t1 * 32 + lane];
                        float4 u2 = xw4[(size_t)t2 * 32 + lane];
                        float4 u3 = xw4[(size_t)t3 * 32 + lane];
                        acc.x = fmaf(v0.x, d0, fmaf(v1.x, d1, fmaf(v2.x, d2, fmaf(v3.x, d3, acc.x))));
                        acc.y = fmaf(v0.y, d0, fmaf(v1.y, d1, fmaf(v2.y, d2, fmaf(v3.y, d3, acc.y))));
                        acc.z = fmaf(v0.z, d0, fmaf(v1.z, d1, fmaf(v2.z, d2, fmaf(v3.z, d3, acc.z))));
                        acc.w = fmaf(v0.w, d0, fmaf(v1.w, d1, fmaf(v2.w, d2, fmaf(v3.w, d3, acc.w))));
                        v0 = u0; v1 = u1; v2 = u2; v3 = u3;
                        d0 = e0; d1 = e1; d2 = e2; d3 = e3;
                    }
                    acc.x = fmaf(v0.x, d0, fmaf(v1.x, d1, fmaf(v2.x, d2, fmaf(v3.x, d3, acc.x))));
                    acc.y = fmaf(v0.y, d0, fmaf(v1.y, d1, fmaf(v2.y, d2, fmaf(v3.y, d3, acc.y))));
                    acc.z = fmaf(v0.z, d0, fmaf(v1.z, d1, fmaf(v2.z, d2, fmaf(v3.z, d3, acc.z))));
                    acc.w = fmaf(v0.w, d0, fmaf(v1.w, d1, fmaf(v2.w, d2, fmaf(v3.w, d3, acc.w))));
                }
                for (; j < end; j++) {
                    int s = g_esrc[j];
                    float dv = g_dinv[s];
                    float4 v = xw4[(size_t)s * 32 + lane];
                    acc.x = fmaf(v.x, dv, acc.x); acc.y = fmaf(v.y, dv, acc.y);
                    acc.z = fmaf(v.z, dv, acc.z); acc.w = fmaf(v.w, dv, acc.w);
                }
                float4 xv = x4[(size_t)node * 32 + lane];
                hv.x = fmaxf(fmaf(dvd, acc.x, bgv.x), 0.f) + xv.x;
                hv.y = fmaxf(fmaf(dvd, acc.y, bgv.y), 0.f) + xv.y;
                hv.z = fmaxf(fmaf(dvd, acc.z, bgv2.x), 0.f) + xv.z;
                hv.w = fmaxf(fmaf(dvd, acc.w, bgv2.y), 0.f) + xv.w;
            }
            ((float4*)(sh + rr * 128))[lane] = hv;
        }
    }

    // ---- stage B: h1 = relu(h @ W1 + b1), W1 streamed in 2 halves ----
    {
        float2 acc[8][2];
#pragma unroll
        for (int ri = 0; ri < 8; ri++) {
            acc[ri][0] = make_float2(0.f, 0.f);
            acc[ri][1] = make_float2(0.f, 0.f);
        }
        const float* hbase = sh + w * 8 * 128;
#pragma unroll 1
        for (int half = 0; half < 2; half++) {
            __syncthreads();  // previous wbuf consumers done (also orders stage A)
            {
                float4* d4 = (float4*)wbuf;
                const float4* s4 = (const float4*)(W1 + half * 8192);
                for (int i = tid; i < 2048; i += 256) d4[i] = s4[i];
            }
            __syncthreads();
            int kb = half * 64;
            float4 wv[4];
#pragma unroll
            for (int kk = 0; kk < 4; kk++)
                wv[kk] = ((const float4*)(wbuf + kk * 128))[lane];
#pragma unroll 2
            for (int k0 = 0; k0 < 60; k0 += 4) {
                float4 wn[4];
#pragma unroll
                for (int kk = 0; kk < 4; kk++)
                    wn[kk] = ((const float4*)(wbuf + (k0 + 4 + kk) * 128))[lane];
                gemm_step8(acc, hbase, kb + k0, wv);
#pragma unroll
                for (int kk = 0; kk < 4; kk++) wv[kk] = wn[kk];
            }
            gemm_step8(acc, hbase, kb + 60, wv);
        }
#pragma unroll
        for (int ri = 0; ri < 8; ri++) {
            int rr = w * 8 + ri;
            float4 o;
            o.x = fmaxf(acc[ri][0].x + sb1[lane * 4 + 0], 0.f);
            o.y = fmaxf(acc[ri][0].y + sb1[lane * 4 + 1], 0.f);
            o.z = fmaxf(acc[ri][1].x + sb1[lane * 4 + 2], 0.f);
            o.w = fmaxf(acc[ri][1].y + sb1[lane * 4 + 3], 0.f);
            ((float4*)(sh1 + rr * 128))[lane] = o;
        }
    }

    // ---- stage C: h2 = relu(h1 @ W2 + b2) -> sh [64][64] ----
    {
        __syncthreads();  // all warps done reading wbuf (stage B)
        {
            float4* d4 = (float4*)wbuf;
            const float4* s4 = (const float4*)W2;
            for (int i = tid; i < 2048; i += 256) d4[i] = s4[i];
        }
        __syncthreads();

        float2 acc2[8];
#pragma unroll
        for (int ri = 0; ri < 8; ri++) acc2[ri] = make_float2(0.f, 0.f);
        const float* hbase = sh1 + w * 8 * 128;
        float2 wv2[4];
#pragma unroll
        for (int kk = 0; kk < 4; kk++)
            wv2[kk] = ((const float2*)(wbuf + kk * 64))[lane];
#pragma unroll 2
        for (int k0 = 0; k0 < 128; k0 += 4) {
            float2 wn2[4];
            if (k0 + 4 < 128) {
#pragma unroll
                for (int kk = 0; kk < 4; kk++)
                    wn2[kk] = ((const float2*)(wbuf + (k0 + 4 + kk) * 64))[lane];
            }
#pragma unroll
            for (int ri = 0; ri < 8; ri++) {
                float4 xv = *(const float4*)(hbase + ri * 128 + k0);
                ffma2(acc2[ri], make_float2(xv.x, xv.x), wv2[0]);
                ffma2(acc2[ri], make_float2(xv.y, xv.y), wv2[1]);
                ffma2(acc2[ri], make_float2(xv.z, xv.z), wv2[2]);
                ffma2(acc2[ri], make_float2(xv.w, xv.w), wv2[3]);
            }
#pragma unroll
            for (int kk = 0; kk < 4; kk++) wv2[kk] = wn2[kk];
        }
#pragma unroll
        for (int ri = 0; ri < 8; ri++) {
            int rr = w * 8 + ri;
            float2 o;
            o.x = fmaxf(acc2[ri].x + sb2[lane * 2 + 0], 0.f);
            o.y = fmaxf(acc2[ri].y + sb2[lane * 2 + 1], 0.f);
            ((float2*)(sh + rr * 64))[lane] = o;   // own rows (stage A done long ago)
        }
    }
    __syncthreads();

    // ---- stage D: out = h2 @ W3 + b3 ----
    if (tid < 128) {
        int r = tid >> 1, c = tid & 1;
        float a = sb3[c];
#pragma unroll
        for (int k = 0; k < 64; k++) a = fmaf(sh[r * 64 + k], sW3[k * 2 + c], a);
        int node = rbase + r;
        if (node < n) out[(size_t)c * n + node] = a;
    }
}

// ---------------------------------------------------------------------------
extern "C" void kernel_launch(void* const* d_in, const int* in_sizes, int n_in,
                              void* d_out, int out_size) {
    const float* x  = (const float*)d_in[0];
    const int*   ei = (const int*)d_in[1];
    const float* Wg = (const float*)d_in[2];
    const float* bg = (const float*)d_in[3];
    const float* W1 = (const float*)d_in[4];
    const float* b1 = (const float*)d_in[5];
    const float* W2 = (const float*)d_in[6];
    const float* b2 = (const float*)d_in[7];
    const float* W3 = (const float*)d_in[8];
    const float* b3 = (const float*)d_in[9];
    float* out = (float*)d_out;

    int n = in_sizes[0] / DF;
    int e = in_sizes[1] / 2;
    int nb = (n + 1023) / 1024;

    const int gemm_smem = (16384 + 8192) * 4;              // 98304
    const int mlp_smem  = (3 * 8192 + 450) * 4;            // 100104
    cudaFuncSetAttribute(k_gemm_xw, cudaFuncAttributeMaxDynamicSharedMemorySize, gemm_smem);
    cudaFuncSetAttribute(k_mlp, cudaFuncAttributeMaxDynamicSharedMemorySize, mlp_smem);

    void* ecnt_ptr = nullptr;
    cudaGetSymbolAddress(&ecnt_ptr, g_ecnt);

    // Fork s2 at t=0: GEMM depends only on inputs — overlaps the whole CSR build.
    cudaEventRecord(g_ev_root, 0);
    cudaStreamWaitEvent(g_s2, g_ev_root, 0);
    k_gemm_xw<<<(n + 63) / 64, 256, gemm_smem, g_s2>>>(x, Wg, n);
    cudaEventRecord(g_ev_gemm, g_s2);

    // Main stream: CSR build (memory/atomic-bound, hides under the GEMM).
    cudaMemsetAsync(ecnt_ptr, 0, (size_t)n * sizeof(int), 0);
    k_count<<<(e + 255) / 256, 256>>>(ei, e);
    k_dinv<<<(n + 255) / 256, 256>>>(n);
    k_scan1<<<nb, 1024>>>(n);
    k_scan2<<<1, 32>>>(nb);
    k_scan3<<<nb, 1024>>>(n);
    k_fill<<<(e + 255) / 256, 256>>>(ei, e);

    // Join: fused gather+MLP, 2 CTAs/SM for gather/compute overlap.
    cudaStreamWaitEvent(0, g_ev_gemm, 0);
    k_mlp<<<(n + 63) / 64, 256, mlp_smem>>>(x, bg, W1, b1, W2, b2, W3, b3, out, n);
}

// round 13
// speedup vs baseline: 1.1523x; 1.1523x over previous
#include <cuda_runtime.h>
#include <cstdint>

#define DF 128
#define MAXN 50000
#define MAXE 800000

// Scratch (allocation-free rule: __device__ globals)
__device__ __align__(16) float g_xw[MAXN * DF];    // x @ Wg (no dinv)
__device__ float g_dinv[MAXN];
__device__ int   g_ecnt[MAXN];
__device__ int   g_off[MAXN + 1];
__device__ int   g_cur[MAXN];
__device__ int   g_esrc[MAXE];
__device__ int   g_bsum[64];
__device__ int   g_total;

// Packed fp32x2 FMA (SASS FFMA2): c += a * b on both lanes, exact fp32.
__device__ __forceinline__ void ffma2(float2& c, const float2 a, const float2 b) {
    asm("fma.rn.f32x2 %0, %1, %2, %0;"
        : "+l"(reinterpret_cast<unsigned long long&>(c))
        : "l"(reinterpret_cast<const unsigned long long&>(a)),
          "l"(reinterpret_cast<const unsigned long long&>(b)));
}

// Stream + events for graph-captured fork/join (created at load time).
static cudaStream_t g_s2;
static cudaEvent_t g_ev_root, g_ev_gemm;
static struct StreamInit {
    StreamInit() {
        cudaStreamCreateWithFlags(&g_s2, cudaStreamNonBlocking);
        cudaEventCreateWithFlags(&g_ev_root, cudaEventDisableTiming);
        cudaEventCreateWithFlags(&g_ev_gemm, cudaEventDisableTiming);
    }
} g_stream_init;

// ---------------------------------------------------------------------------
__global__ void k_count(const int* __restrict__ ei, int e) {
    int i = blockIdx.x * blockDim.x + threadIdx.x;
    if (i < e) atomicAdd(&g_ecnt[ei[e + i]], 1);
}

__global__ void k_dinv(int n) {
    int i = blockIdx.x * blockDim.x + threadIdx.x;
    if (i < n) g_dinv[i] = rsqrtf((float)(g_ecnt[i] + 1));  // +1 self loop
}

__global__ __launch_bounds__(1024) void k_scan1(int n) {
    __shared__ int wsum[32];
    int tid = threadIdx.x, lane = tid & 31, wid = tid >> 5;
    int i = blockIdx.x * 1024 + tid;
    int v = (i < n) ? g_ecnt[i] : 0;
    int s = v;
#pragma unroll
    for (int d = 1; d < 32; d <<= 1) {
        int t = __shfl_up_sync(0xffffffffu, s, d);
        if (lane >= d) s += t;
    }
    if (lane == 31) wsum[wid] = s;
    __syncthreads();
    if (wid == 0) {
        int t = wsum[lane];
#pragma unroll
        for (int d = 1; d < 32; d <<= 1) {
            int u = __shfl_up_sync(0xffffffffu, t, d);
            if (lane >= d) t += u;
        }
        wsum[lane] = t;
    }
    __syncthreads();
    int excl = s - v + (wid ? wsum[wid - 1] : 0);
    if (i < n) g_off[i] = excl;
    if (tid == 1023) g_bsum[blockIdx.x] = excl + v;
}

__global__ void k_scan2(int nb) {
    if (threadIdx.x == 0 && blockIdx.x == 0) {
        int run = 0;
        for (int i = 0; i < nb; i++) { int t = g_bsum[i]; g_bsum[i] = run; run += t; }
        g_total = run;
    }
}

__global__ __launch_bounds__(1024) void k_scan3(int n) {
    int i = blockIdx.x * 1024 + threadIdx.x;
    if (i < n) {
        int off = g_off[i] + g_bsum[blockIdx.x];
        g_off[i] = off;
        g_cur[i] = off;
    }
    if (i == 0) g_off[n] = g_total;
}

__global__ void k_fill(const int* __restrict__ ei, int e) {
    int i = blockIdx.x * blockDim.x + threadIdx.x;
    if (i < e) {
        int s = ei[i];
        int d = ei[e + i];
        int pos = atomicAdd(&g_cur[d], 1);
        g_esrc[pos] = s;
    }
}

// ---------------------------------------------------------------------------
// xw = x @ Wg. 64 rows/block, 256 threads (8 warps), 2 CTA/SM.
__global__ __launch_bounds__(256) void k_gemm_xw(const float* __restrict__ x,
                                                 const float* __restrict__ Wg,
                                                 int n) {
    extern __shared__ float sm[];
    float* ws = sm;              // [128][128] 64KB
    float* xs = sm + 16384;      // [64][128]  32KB
    int tid = threadIdx.x;

    float4* ws4 = (float4*)ws;
    const float4* Wg4 = (const float4*)Wg;
    for (int i = tid; i < 4096; i += 256) ws4[i] = Wg4[i];

    int rbase = blockIdx.x * 64;
    float4* xs4 = (float4*)xs;
    const float4* x4 = (const float4*)x;
    for (int i = tid; i < 2048; i += 256) {
        int r = rbase + (i >> 5);
        xs4[i] = (r < n) ? x4[(size_t)r * 32 + (i & 31)]
                         : make_float4(0.f, 0.f, 0.f, 0.f);
    }
    __syncthreads();

    int w = tid >> 5, lane = tid & 31;
    float2 acc[8][2];
#pragma unroll
    for (int ri = 0; ri < 8; ri++) {
        acc[ri][0] = make_float2(0.f, 0.f);
        acc[ri][1] = make_float2(0.f, 0.f);
    }

    const float* xbase = xs + w * 8 * 128;
    for (int k0 = 0; k0 < 128; k0 += 4) {
        float4 wv[4];
#pragma unroll
        for (int kk = 0; kk < 4; kk++)
            wv[kk] = ((const float4*)(ws + (k0 + kk) * 128))[lane];
#pragma unroll
        for (int ri = 0; ri < 8; ri++) {
            float4 xv = *(const float4*)(xbase + ri * 128 + k0);
            ffma2(acc[ri][0], make_float2(xv.x, xv.x), make_float2(wv[0].x, wv[0].y));
            ffma2(acc[ri][1], make_float2(xv.x, xv.x), make_float2(wv[0].z, wv[0].w));
            ffma2(acc[ri][0], make_float2(xv.y, xv.y), make_float2(wv[1].x, wv[1].y));
            ffma2(acc[ri][1], make_float2(xv.y, xv.y), make_float2(wv[1].z, wv[1].w));
            ffma2(acc[ri][0], make_float2(xv.z, xv.z), make_float2(wv[2].x, wv[2].y));
            ffma2(acc[ri][1], make_float2(xv.z, xv.z), make_float2(wv[2].z, wv[2].w));
            ffma2(acc[ri][0], make_float2(xv.w, xv.w), make_float2(wv[3].x, wv[3].y));
            ffma2(acc[ri][1], make_float2(xv.w, xv.w), make_float2(wv[3].z, wv[3].w));
        }
    }

#pragma unroll
    for (int ri = 0; ri < 8; ri++) {
        int r = rbase + w * 8 + ri;
        if (r < n) {
            float4 o = make_float4(acc[ri][0].x, acc[ri][0].y,
                                   acc[ri][1].x, acc[ri][1].y);
            ((float4*)(g_xw + (size_t)r * 128))[lane] = o;
        }
    }
}

// ---------------------------------------------------------------------------
// Fused CSR-gather + epilogue + 3-layer MLP. 64 nodes/CTA, 256 threads,
// ~67KB smem -> 3 CTAs/SM (6 warps/SMSP). Activations are updated IN PLACE:
// each warp reads only its own 8 rows of sh and holds the full output row in
// registers before writing back, so h -> h1 -> h2 share one 32KB buffer.
__global__ __launch_bounds__(256, 3) void k_mlp(const float* __restrict__ x,
                                                const float* __restrict__ bg,
                                                const float* __restrict__ W1,
                                                const float* __restrict__ b1,
                                                const float* __restrict__ W2,
                                                const float* __restrict__ b2,
                                                const float* __restrict__ W3,
                                                const float* __restrict__ b3,
                                                float* __restrict__ out, int n) {
    extern __shared__ float sm[];
    float* wbuf = sm;            // 8192 floats (32KB): W1 half / W2
    float* sh   = wbuf + 8192;   // 8192: h [64][128] -> h1 in place -> h2 (cols 0..63)
    float* sW3 = sh + 8192;      // 128
    float* sb1 = sW3 + 128;      // 128
    float* sbg = sb1 + 128;      // 128
    float* sb2 = sbg + 128;      // 64
    float* sb3 = sb2 + 64;       // 2
    int tid = threadIdx.x;
    int w = tid >> 5, lane = tid & 31;

    if (tid < 128) { sW3[tid] = W3[tid]; sb1[tid] = b1[tid]; sbg[tid] = bg[tid]; }
    else if (tid < 192) sb2[tid - 128] = b2[tid - 128];
    else if (tid < 194) sb3[tid - 192] = b3[tid - 192];
    int rbase = blockIdx.x * 64;
    __syncthreads();

    // ---- stage A: CSR gather + h = relu(dinv*agg + bg) + x, 8 nodes/warp ----
    {
        const float4* xw4 = (const float4*)g_xw;
        const float4* x4 = (const float4*)x;
        float2 bgv = make_float2(sbg[lane * 4 + 0], sbg[lane * 4 + 1]);
        float2 bgv2 = make_float2(sbg[lane * 4 + 2], sbg[lane * 4 + 3]);
#pragma unroll 1
        for (int ri = 0; ri < 8; ri++) {
            int rr = w * 8 + ri;
            int node = rbase + rr;
            float4 hv = make_float4(0.f, 0.f, 0.f, 0.f);
            if (node < n) {
                float dvd = g_dinv[node];
                float4 acc = xw4[(size_t)node * 32 + lane];  // self loop
                acc.x *= dvd; acc.y *= dvd; acc.z *= dvd; acc.w *= dvd;
                int beg = g_off[node], end = g_off[node + 1];
                int j = beg;
                for (; j + 4 <= end; j += 4) {
                    int s0 = g_esrc[j], s1 = g_esrc[j + 1];
                    int s2 = g_esrc[j + 2], s3 = g_esrc[j + 3];
                    float d0 = g_dinv[s0], d1 = g_dinv[s1];
                    float d2 = g_dinv[s2], d3 = g_dinv[s3];
                    float4 v0 = xw4[(size_t)s0 * 32 + lane];
                    float4 v1 = xw4[(size_t)s1 * 32 + lane];
                    float4 v2 = xw4[(size_t)s2 * 32 + lane];
                    float4 v3 = xw4[(size_t)s3 * 32 + lane];
                    acc.x = fmaf(v0.x, d0, fmaf(v1.x, d1, fmaf(v2.x, d2, fmaf(v3.x, d3, acc.x))));
                    acc.y = fmaf(v0.y, d0, fmaf(v1.y, d1, fmaf(v2.y, d2, fmaf(v3.y, d3, acc.y))));
                    acc.z = fmaf(v0.z, d0, fmaf(v1.z, d1, fmaf(v2.z, d2, fmaf(v3.z, d3, acc.z))));
                    acc.w = fmaf(v0.w, d0, fmaf(v1.w, d1, fmaf(v2.w, d2, fmaf(v3.w, d3, acc.w))));
                }
                for (; j < end; j++) {
                    int s = g_esrc[j];
                    float dv = g_dinv[s];
                    float4 v = xw4[(size_t)s * 32 + lane];
                    acc.x = fmaf(v.x, dv, acc.x); acc.y = fmaf(v.y, dv, acc.y);
                    acc.z = fmaf(v.z, dv, acc.z); acc.w = fmaf(v.w, dv, acc.w);
                }
                float4 xv = x4[(size_t)node * 32 + lane];
                hv.x = fmaxf(fmaf(dvd, acc.x, bgv.x), 0.f) + xv.x;
                hv.y = fmaxf(fmaf(dvd, acc.y, bgv.y), 0.f) + xv.y;
                hv.z = fmaxf(fmaf(dvd, acc.z, bgv2.x), 0.f) + xv.z;
                hv.w = fmaxf(fmaf(dvd, acc.w, bgv2.y), 0.f) + xv.w;
            }
            ((float4*)(sh + rr * 128))[lane] = hv;
        }
    }

    // ---- stage B: h1 = relu(h @ W1 + b1), W1 streamed in 2 halves,
    //      h1 written IN PLACE over h (own rows only, after all own reads) ----
    {
        float2 acc[8][2];
#pragma unroll
        for (int ri = 0; ri < 8; ri++) {
            acc[ri][0] = make_float2(0.f, 0.f);
            acc[ri][1] = make_float2(0.f, 0.f);
        }
        const float* hbase = sh + w * 8 * 128;
#pragma unroll 1
        for (int half = 0; half < 2; half++) {
            __syncthreads();  // previous wbuf consumers done (also orders stage A)
            {
                float4* d4 = (float4*)wbuf;
                const float4* s4 = (const float4*)(W1 + half * 8192);
                for (int i = tid; i < 2048; i += 256) d4[i] = s4[i];
            }
            __syncthreads();
            int kb = half * 64;
            for (int k0 = 0; k0 < 64; k0 += 4) {
                float4 wv[4];
#pragma unroll
                for (int kk = 0; kk < 4; kk++)
                    wv[kk] = ((const float4*)(wbuf + (k0 + kk) * 128))[lane];
#pragma unroll
                for (int ri = 0; ri < 8; ri++) {
                    float4 xv = *(const float4*)(hbase + ri * 128 + kb + k0);
                    ffma2(acc[ri][0], make_float2(xv.x, xv.x), make_float2(wv[0].x, wv[0].y));
                    ffma2(acc[ri][1], make_float2(xv.x, xv.x), make_float2(wv[0].z, wv[0].w));
                    ffma2(acc[ri][0], make_float2(xv.y, xv.y), make_float2(wv[1].x, wv[1].y));
                    ffma2(acc[ri][1], make_float2(xv.y, xv.y), make_float2(wv[1].z, wv[1].w));
                    ffma2(acc[ri][0], make_float2(xv.z, xv.z), make_float2(wv[2].x, wv[2].y));
                    ffma2(acc[ri][1], make_float2(xv.z, xv.z), make_float2(wv[2].z, wv[2].w));
                    ffma2(acc[ri][0], make_float2(xv.w, xv.w), make_float2(wv[3].x, wv[3].y));
                    ffma2(acc[ri][1], make_float2(xv.w, xv.w), make_float2(wv[3].z, wv[3].w));
                }
            }
        }
        // all reads of own h rows complete; overwrite with h1
#pragma unroll
        for (int ri = 0; ri < 8; ri++) {
            int rr = w * 8 + ri;
            float4 o;
            o.x = fmaxf(acc[ri][0].x + sb1[lane * 4 + 0], 0.f);
            o.y = fmaxf(acc[ri][0].y + sb1[lane * 4 + 1], 0.f);
            o.z = fmaxf(acc[ri][1].x + sb1[lane * 4 + 2], 0.f);
            o.w = fmaxf(acc[ri][1].y + sb1[lane * 4 + 3], 0.f);
            ((float4*)(sh + rr * 128))[lane] = o;
        }
    }

    // ---- stage C: h2 = relu(h1 @ W2 + b2), written IN PLACE into cols 0..63
    //      of own rows (stride 128) after all own reads ----
    {
        __syncthreads();  // all warps done reading wbuf (stage B)
        {
            float4* d4 = (float4*)wbuf;
            const float4* s4 = (const float4*)W2;
            for (int i = tid; i < 2048; i += 256) d4[i] = s4[i];
        }
        __syncthreads();

        float2 acc2[8];
#pragma unroll
        for (int ri = 0; ri < 8; ri++) acc2[ri] = make_float2(0.f, 0.f);
        const float* hbase = sh + w * 8 * 128;
        for (int k0 = 0; k0 < 128; k0 += 4) {
            float2 wv2[4];
#pragma unroll
            for (int kk = 0; kk < 4; kk++)
                wv2[kk] = ((const float2*)(wbuf + (k0 + kk) * 64))[lane];
#pragma unroll
            for (int ri = 0; ri < 8; ri++) {
                float4 xv = *(const float4*)(hbase + ri * 128 + k0);
                ffma2(acc2[ri], make_float2(xv.x, xv.x), wv2[0]);
                ffma2(acc2[ri], make_float2(xv.y, xv.y), wv2[1]);
                ffma2(acc2[ri], make_float2(xv.z, xv.z), wv2[2]);
                ffma2(acc2[ri], make_float2(xv.w, xv.w), wv2[3]);
            }
        }
#pragma unroll
        for (int ri = 0; ri < 8; ri++) {
            int rr = w * 8 + ri;
            float2 o;
            o.x = fmaxf(acc2[ri].x + sb2[lane * 2 + 0], 0.f);
            o.y = fmaxf(acc2[ri].y + sb2[lane * 2 + 1], 0.f);
            ((float2*)(sh + rr * 128))[lane] = o;   // own row, cols 0..63
        }
    }
    __syncthreads();

    // ---- stage D: out = h2 @ W3 + b3 (h2 at stride 128, cols 0..63) ----
    if (tid < 128) {
        int r = tid >> 1, c = tid & 1;
        float a = sb3[c];
#pragma unroll
        for (int k = 0; k < 64; k++) a = fmaf(sh[r * 128 + k], sW3[k * 2 + c], a);
        int node = rbase + r;
        if (node < n) out[(size_t)c * n + node] = a;
    }
}

// ---------------------------------------------------------------------------
extern "C" void kernel_launch(void* const* d_in, const int* in_sizes, int n_in,
                              void* d_out, int out_size) {
    const float* x  = (const float*)d_in[0];
    const int*   ei = (const int*)d_in[1];
    const float* Wg = (const float*)d_in[2];
    const float* bg = (const float*)d_in[3];
    const float* W1 = (const float*)d_in[4];
    const float* b1 = (const float*)d_in[5];
    const float* W2 = (const float*)d_in[6];
    const float* b2 = (const float*)d_in[7];
    const float* W3 = (const float*)d_in[8];
    const float* b3 = (const float*)d_in[9];
    float* out = (float*)d_out;

    int n = in_sizes[0] / DF;
    int e = in_sizes[1] / 2;
    int nb = (n + 1023) / 1024;

    const int gemm_smem = (16384 + 8192) * 4;              // 98304
    const int mlp_smem  = (2 * 8192 + 450) * 4;            // 67336
    cudaFuncSetAttribute(k_gemm_xw, cudaFuncAttributeMaxDynamicSharedMemorySize, gemm_smem);
    cudaFuncSetAttribute(k_mlp, cudaFuncAttributeMaxDynamicSharedMemorySize, mlp_smem);

    void* ecnt_ptr = nullptr;
    cudaGetSymbolAddress(&ecnt_ptr, g_ecnt);

    // Fork s2 at t=0: GEMM depends only on inputs — overlaps the whole CSR build.
    cudaEventRecord(g_ev_root, 0);
    cudaStreamWaitEvent(g_s2, g_ev_root, 0);
    k_gemm_xw<<<(n + 63) / 64, 256, gemm_smem, g_s2>>>(x, Wg, n);
    cudaEventRecord(g_ev_gemm, g_s2);

    // Main stream: CSR build (memory/atomic-bound, hides under the GEMM).
    cudaMemsetAsync(ecnt_ptr, 0, (size_t)n * sizeof(int), 0);
    k_count<<<(e + 255) / 256, 256>>>(ei, e);
    k_dinv<<<(n + 255) / 256, 256>>>(n);
    k_scan1<<<nb, 1024>>>(n);
    k_scan2<<<1, 32>>>(nb);
    k_scan3<<<nb, 1024>>>(n);
    k_fill<<<(e + 255) / 256, 256>>>(ei, e);

    // Join: fused gather+MLP, 3 CTAs/SM (gather latency hiding + phase desync).
    cudaStreamWaitEvent(0, g_ev_gemm, 0);
    k_mlp<<<(n + 63) / 64, 256, mlp_smem>>>(x, bg, W1, b1, W2, b2, W3, b3, out, n);
}

// round 14
// speedup vs baseline: 1.1623x; 1.0087x over previous
#include <cuda_runtime.h>
#include <cstdint>

#define DF 128
#define MAXN 50000
#define MAXE 800000

// Scratch (allocation-free rule: __device__ globals)
__device__ __align__(16) float g_xw[MAXN * DF];    // x @ Wg (no dinv)
__device__ float g_dinv[MAXN];
__device__ int   g_ecnt[MAXN];
__device__ int   g_off[MAXN + 1];
__device__ int   g_cur[MAXN];
__device__ int   g_esrc[MAXE];
__device__ int   g_bsum[64];
__device__ int   g_total;

// Packed fp32x2 FMA (SASS FFMA2): c += a * b on both lanes, exact fp32.
__device__ __forceinline__ void ffma2(float2& c, const float2 a, const float2 b) {
    asm("fma.rn.f32x2 %0, %1, %2, %0;"
        : "+l"(reinterpret_cast<unsigned long long&>(c))
        : "l"(reinterpret_cast<const unsigned long long&>(a)),
          "l"(reinterpret_cast<const unsigned long long&>(b)));
}

// Stream + events for graph-captured fork/join (created at load time).
static cudaStream_t g_s2;
static cudaEvent_t g_ev_root, g_ev_gemm;
static struct StreamInit {
    StreamInit() {
        cudaStreamCreateWithFlags(&g_s2, cudaStreamNonBlocking);
        cudaEventCreateWithFlags(&g_ev_root, cudaEventDisableTiming);
        cudaEventCreateWithFlags(&g_ev_gemm, cudaEventDisableTiming);
    }
} g_stream_init;

// ---------------------------------------------------------------------------
__global__ void k_count(const int* __restrict__ ei, int e) {
    int i = blockIdx.x * blockDim.x + threadIdx.x;
    if (i < e) atomicAdd(&g_ecnt[ei[e + i]], 1);
}

__global__ void k_dinv(int n) {
    int i = blockIdx.x * blockDim.x + threadIdx.x;
    if (i < n) g_dinv[i] = rsqrtf((float)(g_ecnt[i] + 1));  // +1 self loop
}

__global__ __launch_bounds__(1024) void k_scan1(int n) {
    __shared__ int wsum[32];
    int tid = threadIdx.x, lane = tid & 31, wid = tid >> 5;
    int i = blockIdx.x * 1024 + tid;
    int v = (i < n) ? g_ecnt[i] : 0;
    int s = v;
#pragma unroll
    for (int d = 1; d < 32; d <<= 1) {
        int t = __shfl_up_sync(0xffffffffu, s, d);
        if (lane >= d) s += t;
    }
    if (lane == 31) wsum[wid] = s;
    __syncthreads();
    if (wid == 0) {
        int t = wsum[lane];
#pragma unroll
        for (int d = 1; d < 32; d <<= 1) {
            int u = __shfl_up_sync(0xffffffffu, t, d);
            if (lane >= d) t += u;
        }
        wsum[lane] = t;
    }
    __syncthreads();
    int excl = s - v + (wid ? wsum[wid - 1] : 0);
    if (i < n) g_off[i] = excl;
    if (tid == 1023) g_bsum[blockIdx.x] = excl + v;
}

__global__ void k_scan2(int nb) {
    if (threadIdx.x == 0 && blockIdx.x == 0) {
        int run = 0;
        for (int i = 0; i < nb; i++) { int t = g_bsum[i]; g_bsum[i] = run; run += t; }
        g_total = run;
    }
}

__global__ __launch_bounds__(1024) void k_scan3(int n) {
    int i = blockIdx.x * 1024 + threadIdx.x;
    if (i < n) {
        int off = g_off[i] + g_bsum[blockIdx.x];
        g_off[i] = off;
        g_cur[i] = off;
    }
    if (i == 0) g_off[n] = g_total;
}

__global__ void k_fill(const int* __restrict__ ei, int e) {
    int i = blockIdx.x * blockDim.x + threadIdx.x;
    if (i < e) {
        int s = ei[i];
        int d = ei[e + i];
        int pos = atomicAdd(&g_cur[d], 1);
        g_esrc[pos] = s;
    }
}

// ---------------------------------------------------------------------------
// xw = x @ Wg. 64 rows/block, 256 threads (8 warps).
// Wg streamed through a 32KB buffer in 2 halves -> ~64KB smem -> 3 CTAs/SM
// (6 warps/SMSP). Accumulators persist in registers across the reload.
__global__ __launch_bounds__(256, 3) void k_gemm_xw(const float* __restrict__ x,
                                                    const float* __restrict__ Wg,
                                                    int n) {
    extern __shared__ float sm[];
    float* wbuf = sm;            // 8192 floats (32KB): half of Wg [64][128]
    float* xs = sm + 8192;       // 8192: x tile [64][128]
    int tid = threadIdx.x;

    int rbase = blockIdx.x * 64;
    float4* xs4 = (float4*)xs;
    const float4* x4 = (const float4*)x;
    for (int i = tid; i < 2048; i += 256) {
        int r = rbase + (i >> 5);
        xs4[i] = (r < n) ? x4[(size_t)r * 32 + (i & 31)]
                         : make_float4(0.f, 0.f, 0.f, 0.f);
    }

    int w = tid >> 5, lane = tid & 31;
    float2 acc[8][2];
#pragma unroll
    for (int ri = 0; ri < 8; ri++) {
        acc[ri][0] = make_float2(0.f, 0.f);
        acc[ri][1] = make_float2(0.f, 0.f);
    }

    const float* xbase = xs + w * 8 * 128;
#pragma unroll 1
    for (int half = 0; half < 2; half++) {
        __syncthreads();  // previous wbuf consumers done (iter0: orders xs fill)
        {
            float4* d4 = (float4*)wbuf;
            const float4* s4 = (const float4*)(Wg + half * 8192);
            for (int i = tid; i < 2048; i += 256) d4[i] = s4[i];
        }
        __syncthreads();
        int kb = half * 64;
        for (int k0 = 0; k0 < 64; k0 += 4) {
            float4 wv[4];
#pragma unroll
            for (int kk = 0; kk < 4; kk++)
                wv[kk] = ((const float4*)(wbuf + (k0 + kk) * 128))[lane];
#pragma unroll
            for (int ri = 0; ri < 8; ri++) {
                float4 xv = *(const float4*)(xbase + ri * 128 + kb + k0);
                ffma2(acc[ri][0], make_float2(xv.x, xv.x), make_float2(wv[0].x, wv[0].y));
                ffma2(acc[ri][1], make_float2(xv.x, xv.x), make_float2(wv[0].z, wv[0].w));
                ffma2(acc[ri][0], make_float2(xv.y, xv.y), make_float2(wv[1].x, wv[1].y));
                ffma2(acc[ri][1], make_float2(xv.y, xv.y), make_float2(wv[1].z, wv[1].w));
                ffma2(acc[ri][0], make_float2(xv.z, xv.z), make_float2(wv[2].x, wv[2].y));
                ffma2(acc[ri][1], make_float2(xv.z, xv.z), make_float2(wv[2].z, wv[2].w));
                ffma2(acc[ri][0], make_float2(xv.w, xv.w), make_float2(wv[3].x, wv[3].y));
                ffma2(acc[ri][1], make_float2(xv.w, xv.w), make_float2(wv[3].z, wv[3].w));
            }
        }
    }

#pragma unroll
    for (int ri = 0; ri < 8; ri++) {
        int r = rbase + w * 8 + ri;
        if (r < n) {
            float4 o = make_float4(acc[ri][0].x, acc[ri][0].y,
                                   acc[ri][1].x, acc[ri][1].y);
            ((float4*)(g_xw + (size_t)r * 128))[lane] = o;
        }
    }
}

// ---------------------------------------------------------------------------
// Fused CSR-gather + epilogue + 3-layer MLP. 64 nodes/CTA, 256 threads,
// ~67KB smem -> 3 CTAs/SM (6 warps/SMSP). Activations updated IN PLACE.
__global__ __launch_bounds__(256, 3) void k_mlp(const float* __restrict__ x,
                                                const float* __restrict__ bg,
                                                const float* __restrict__ W1,
                                                const float* __restrict__ b1,
                                                const float* __restrict__ W2,
                                                const float* __restrict__ b2,
                                                const float* __restrict__ W3,
                                                const float* __restrict__ b3,
                                                float* __restrict__ out, int n) {
    extern __shared__ float sm[];
    float* wbuf = sm;            // 8192 floats (32KB): W1 half / W2
    float* sh   = wbuf + 8192;   // 8192: h [64][128] -> h1 in place -> h2 (cols 0..63)
    float* sW3 = sh + 8192;      // 128
    float* sb1 = sW3 + 128;      // 128
    float* sbg = sb1 + 128;      // 128
    float* sb2 = sbg + 128;      // 64
    float* sb3 = sb2 + 64;       // 2
    int tid = threadIdx.x;
    int w = tid >> 5, lane = tid & 31;

    if (tid < 128) { sW3[tid] = W3[tid]; sb1[tid] = b1[tid]; sbg[tid] = bg[tid]; }
    else if (tid < 192) sb2[tid - 128] = b2[tid - 128];
    else if (tid < 194) sb3[tid - 192] = b3[tid - 192];
    int rbase = blockIdx.x * 64;
    __syncthreads();

    // ---- stage A: CSR gather + h = relu(dinv*agg + bg) + x, 8 nodes/warp ----
    {
        const float4* xw4 = (const float4*)g_xw;
        const float4* x4 = (const float4*)x;
        float2 bgv = make_float2(sbg[lane * 4 + 0], sbg[lane * 4 + 1]);
        float2 bgv2 = make_float2(sbg[lane * 4 + 2], sbg[lane * 4 + 3]);
#pragma unroll 1
        for (int ri = 0; ri < 8; ri++) {
            int rr = w * 8 + ri;
            int node = rbase + rr;
            float4 hv = make_float4(0.f, 0.f, 0.f, 0.f);
            if (node < n) {
                float dvd = g_dinv[node];
                float4 acc = xw4[(size_t)node * 32 + lane];  // self loop
                acc.x *= dvd; acc.y *= dvd; acc.z *= dvd; acc.w *= dvd;
                int beg = g_off[node], end = g_off[node + 1];
                int j = beg;
                for (; j + 4 <= end; j += 4) {
                    int s0 = g_esrc[j], s1 = g_esrc[j + 1];
                    int s2 = g_esrc[j + 2], s3 = g_esrc[j + 3];
                    float d0 = g_dinv[s0], d1 = g_dinv[s1];
                    float d2 = g_dinv[s2], d3 = g_dinv[s3];
                    float4 v0 = xw4[(size_t)s0 * 32 + lane];
                    float4 v1 = xw4[(size_t)s1 * 32 + lane];
                    float4 v2 = xw4[(size_t)s2 * 32 + lane];
                    float4 v3 = xw4[(size_t)s3 * 32 + lane];
                    acc.x = fmaf(v0.x, d0, fmaf(v1.x, d1, fmaf(v2.x, d2, fmaf(v3.x, d3, acc.x))));
                    acc.y = fmaf(v0.y, d0, fmaf(v1.y, d1, fmaf(v2.y, d2, fmaf(v3.y, d3, acc.y))));
                    acc.z = fmaf(v0.z, d0, fmaf(v1.z, d1, fmaf(v2.z, d2, fmaf(v3.z, d3, acc.z))));
                    acc.w = fmaf(v0.w, d0, fmaf(v1.w, d1, fmaf(v2.w, d2, fmaf(v3.w, d3, acc.w))));
                }
                for (; j < end; j++) {
                    int s = g_esrc[j];
                    float dv = g_dinv[s];
                    float4 v = xw4[(size_t)s * 32 + lane];
                    acc.x = fmaf(v.x, dv, acc.x); acc.y = fmaf(v.y, dv, acc.y);
                    acc.z = fmaf(v.z, dv, acc.z); acc.w = fmaf(v.w, dv, acc.w);
                }
                float4 xv = x4[(size_t)node * 32 + lane];
                hv.x = fmaxf(fmaf(dvd, acc.x, bgv.x), 0.f) + xv.x;
                hv.y = fmaxf(fmaf(dvd, acc.y, bgv.y), 0.f) + xv.y;
                hv.z = fmaxf(fmaf(dvd, acc.z, bgv2.x), 0.f) + xv.z;
                hv.w = fmaxf(fmaf(dvd, acc.w, bgv2.y), 0.f) + xv.w;
            }
            ((float4*)(sh + rr * 128))[lane] = hv;
        }
    }

    // ---- stage B: h1 = relu(h @ W1 + b1), W1 streamed in 2 halves,
    //      h1 written IN PLACE over h (own rows only, after all own reads) ----
    {
        float2 acc[8][2];
#pragma unroll
        for (int ri = 0; ri < 8; ri++) {
            acc[ri][0] = make_float2(0.f, 0.f);
            acc[ri][1] = make_float2(0.f, 0.f);
        }
        const float* hbase = sh + w * 8 * 128;
#pragma unroll 1
        for (int half = 0; half < 2; half++) {
            __syncthreads();  // previous wbuf consumers done (also orders stage A)
            {
                float4* d4 = (float4*)wbuf;
                const float4* s4 = (const float4*)(W1 + half * 8192);
                for (int i = tid; i < 2048; i += 256) d4[i] = s4[i];
            }
            __syncthreads();
            int kb = half * 64;
            for (int k0 = 0; k0 < 64; k0 += 4) {
                float4 wv[4];
#pragma unroll
                for (int kk = 0; kk < 4; kk++)
                    wv[kk] = ((const float4*)(wbuf + (k0 + kk) * 128))[lane];
#pragma unroll
                for (int ri = 0; ri < 8; ri++) {
                    float4 xv = *(const float4*)(hbase + ri * 128 + kb + k0);
                    ffma2(acc[ri][0], make_float2(xv.x, xv.x), make_float2(wv[0].x, wv[0].y));
                    ffma2(acc[ri][1], make_float2(xv.x, xv.x), make_float2(wv[0].z, wv[0].w));
                    ffma2(acc[ri][0], make_float2(xv.y, xv.y), make_float2(wv[1].x, wv[1].y));
                    ffma2(acc[ri][1], make_float2(xv.y, xv.y), make_float2(wv[1].z, wv[1].w));
                    ffma2(acc[ri][0], make_float2(xv.z, xv.z), make_float2(wv[2].x, wv[2].y));
                    ffma2(acc[ri][1], make_float2(xv.z, xv.z), make_float2(wv[2].z, wv[2].w));
                    ffma2(acc[ri][0], make_float2(xv.w, xv.w), make_float2(wv[3].x, wv[3].y));
                    ffma2(acc[ri][1], make_float2(xv.w, xv.w), make_float2(wv[3].z, wv[3].w));
                }
            }
        }
        // all reads of own h rows complete; overwrite with h1
#pragma unroll
        for (int ri = 0; ri < 8; ri++) {
            int rr = w * 8 + ri;
            float4 o;
            o.x = fmaxf(acc[ri][0].x + sb1[lane * 4 + 0], 0.f);
            o.y = fmaxf(acc[ri][0].y + sb1[lane * 4 + 1], 0.f);
            o.z = fmaxf(acc[ri][1].x + sb1[lane * 4 + 2], 0.f);
            o.w = fmaxf(acc[ri][1].y + sb1[lane * 4 + 3], 0.f);
            ((float4*)(sh + rr * 128))[lane] = o;
        }
    }

    // ---- stage C: h2 = relu(h1 @ W2 + b2), written IN PLACE into cols 0..63
    //      of own rows (stride 128) after all own reads ----
    {
        __syncthreads();  // all warps done reading wbuf (stage B)
        {
            float4* d4 = (float4*)wbuf;
            const float4* s4 = (const float4*)W2;
            for (int i = tid; i < 2048; i += 256) d4[i] = s4[i];
        }
        __syncthreads();

        float2 acc2[8];
#pragma unroll
        for (int ri = 0; ri < 8; ri++) acc2[ri] = make_float2(0.f, 0.f);
        const float* hbase = sh + w * 8 * 128;
        for (int k0 = 0; k0 < 128; k0 += 4) {
            float2 wv2[4];
#pragma unroll
            for (int kk = 0; kk < 4; kk++)
                wv2[kk] = ((const float2*)(wbuf + (k0 + kk) * 64))[lane];
#pragma unroll
            for (int ri = 0; ri < 8; ri++) {
                float4 xv = *(const float4*)(hbase + ri * 128 + k0);
                ffma2(acc2[ri], make_float2(xv.x, xv.x), wv2[0]);
                ffma2(acc2[ri], make_float2(xv.y, xv.y), wv2[1]);
                ffma2(acc2[ri], make_float2(xv.z, xv.z), wv2[2]);
                ffma2(acc2[ri], make_float2(xv.w, xv.w), wv2[3]);
            }
        }
#pragma unroll
        for (int ri = 0; ri < 8; ri++) {
            int rr = w * 8 + ri;
            float2 o;
            o.x = fmaxf(acc2[ri].x + sb2[lane * 2 + 0], 0.f);
            o.y = fmaxf(acc2[ri].y + sb2[lane * 2 + 1], 0.f);
            ((float2*)(sh + rr * 128))[lane] = o;   // own row, cols 0..63
        }
    }
    __syncthreads();

    // ---- stage D: out = h2 @ W3 + b3 (h2 at stride 128, cols 0..63) ----
    if (tid < 128) {
        int r = tid >> 1, c = tid & 1;
        float a = sb3[c];
#pragma unroll
        for (int k = 0; k < 64; k++) a = fmaf(sh[r * 128 + k], sW3[k * 2 + c], a);
        int node = rbase + r;
        if (node < n) out[(size_t)c * n + node] = a;
    }
}

// ---------------------------------------------------------------------------
extern "C" void kernel_launch(void* const* d_in, const int* in_sizes, int n_in,
                              void* d_out, int out_size) {
    const float* x  = (const float*)d_in[0];
    const int*   ei = (const int*)d_in[1];
    const float* Wg = (const float*)d_in[2];
    const float* bg = (const float*)d_in[3];
    const float* W1 = (const float*)d_in[4];
    const float* b1 = (const float*)d_in[5];
    const float* W2 = (const float*)d_in[6];
    const float* b2 = (const float*)d_in[7];
    const float* W3 = (const float*)d_in[8];
    const float* b3 = (const float*)d_in[9];
    float* out = (float*)d_out;

    int n = in_sizes[0] / DF;
    int e = in_sizes[1] / 2;
    int nb = (n + 1023) / 1024;

    const int gemm_smem = 2 * 8192 * 4;                    // 65536
    const int mlp_smem  = (2 * 8192 + 450) * 4;            // 67336
    cudaFuncSetAttribute(k_gemm_xw, cudaFuncAttributeMaxDynamicSharedMemorySize, gemm_smem);
    cudaFuncSetAttribute(k_mlp, cudaFuncAttributeMaxDynamicSharedMemorySize, mlp_smem);

    void* ecnt_ptr = nullptr;
    cudaGetSymbolAddress(&ecnt_ptr, g_ecnt);

    // Fork s2 at t=0: GEMM depends only on inputs — overlaps the whole CSR build.
    cudaEventRecord(g_ev_root, 0);
    cudaStreamWaitEvent(g_s2, g_ev_root, 0);
    k_gemm_xw<<<(n + 63) / 64, 256, gemm_smem, g_s2>>>(x, Wg, n);
    cudaEventRecord(g_ev_gemm, g_s2);

    // Main stream: CSR build (memory/atomic-bound, hides under the GEMM).
    cudaMemsetAsync(ecnt_ptr, 0, (size_t)n * sizeof(int), 0);
    k_count<<<(e + 255) / 256, 256>>>(ei, e);
    k_dinv<<<(n + 255) / 256, 256>>>(n);
    k_scan1<<<nb, 1024>>>(n);
    k_scan2<<<1, 32>>>(nb);
    k_scan3<<<nb, 1024>>>(n);
    k_fill<<<(e + 255) / 256, 256>>>(ei, e);

    // Join: fused gather+MLP, 3 CTAs/SM (gather latency hiding + phase desync).
    cudaStreamWaitEvent(0, g_ev_gemm, 0);
    k_mlp<<<(n + 63) / 64, 256, mlp_smem>>>(x, bg, W1, b1, W2, b2, W3, b3, out, n);
}